// round 9
// baseline (speedup 1.0000x reference)
#include <cuda_runtime.h>
#include <cstdint>

// T=32768, H=1024, O=1024
//   scores[t] = enc[t,:] . w_enc  (softmax-invariant decoder term dropped)
//   weights   = softmax(scores)            -> d_out[1024 .. 1024+32768)
//   output[h] = sum_t weights[t]*enc[t,h]  -> d_out[0 .. 1024)
//
// Pure-LDG streaming (no TMA/stage barriers), 256 blocks = 2 CTAs/SM,
// 2-row interleaved pipeline + prefetch.global.L2 3 iterations ahead
// (demand loads hit L2 ~250cyc instead of DRAM ~577cyc -> BDP halves).
// Fused finalize via monotonic-ticket grid sync (all 256 blocks resident).

#define T_ROWS   32768
#define HDIM     1024
#define NBLK     256
#define WARPS    8
#define ROWS_PW  16     // rows per warp: 256*8*16 = 32768
#define ROWS_PB  128    // rows per block

__device__ float g_escore[T_ROWS];
__device__ float g_blk_s[NBLK];
__device__ float g_blk_acc[NBLK * HDIM];
__device__ unsigned int g_done;              // monotonic across graph replays

__global__ __launch_bounds__(256, 2)
void fused_kernel(const float* __restrict__ enc, const float* __restrict__ attn_w,
                  float* __restrict__ out)
{
    __shared__ float4 s_w[256];              // w_enc, 4KB
    __shared__ float4 sm_acc[WARPS * 256];   // 32KB combine scratch
    __shared__ float  sm_s[WARPS];
    __shared__ float  sm_red[32 * 8];
    __shared__ float  sInv;

    const int tid  = threadIdx.x;
    const int lane = tid & 31;
    const int warp = tid >> 5;
    const int bid  = blockIdx.x;

    // w_enc = attn_w[:, O:], O = 1024
    s_w[tid] = ((const float4*)(attn_w + 1024))[tid];
    __syncthreads();

    const float4* __restrict__ enc4 = (const float4*)enc;

    float acc[32];
#pragma unroll
    for (int i = 0; i < 32; i++) acc[i] = 0.0f;
    float s = 0.0f;

    const int row0 = bid * ROWS_PB + warp * ROWS_PW;

    for (int r = 0; r < ROWS_PW; r += 2) {
        const float4* __restrict__ rp0 = enc4 + (size_t)(row0 + r) * 256;
        const float4* __restrict__ rp1 = rp0 + 256;

        // prefetch rows r+6, r+7 into L2 (1 line / lane covers a 4KB row)
        {
            const int pf0 = min(row0 + r + 6, T_ROWS - 1);
            const int pf1 = min(row0 + r + 7, T_ROWS - 1);
            const char* p0 = (const char*)(enc4 + (size_t)pf0 * 256) + lane * 128;
            const char* p1 = (const char*)(enc4 + (size_t)pf1 * 256) + lane * 128;
            asm volatile("prefetch.global.L2 [%0];" :: "l"(p0));
            asm volatile("prefetch.global.L2 [%0];" :: "l"(p1));
        }

        float4 ev0[8], ev1[8];
#pragma unroll
        for (int k = 0; k < 8; k++) ev0[k] = rp0[k * 32 + lane];
#pragma unroll
        for (int k = 0; k < 8; k++) ev1[k] = rp1[k * 32 + lane];

        float d0 = 0.0f, d1 = 0.0f;
#pragma unroll
        for (int k = 0; k < 8; k++) {
            const float4 w = s_w[k * 32 + lane];
            d0 += ev0[k].x * w.x; d0 += ev0[k].y * w.y;
            d0 += ev0[k].z * w.z; d0 += ev0[k].w * w.w;
            d1 += ev1[k].x * w.x; d1 += ev1[k].y * w.y;
            d1 += ev1[k].z * w.z; d1 += ev1[k].w * w.w;
        }
        // two independent butterfly reduces, interleaved
#pragma unroll
        for (int o = 16; o > 0; o >>= 1) {
            d0 += __shfl_xor_sync(0xffffffffu, d0, o);
            d1 += __shfl_xor_sync(0xffffffffu, d1, o);
        }

        const float w0 = __expf(d0);
        const float w1 = __expf(d1);
        if (lane == 0) {
            g_escore[row0 + r]     = w0;
            g_escore[row0 + r + 1] = w1;
        }
        s += w0 + w1;

#pragma unroll
        for (int k = 0; k < 8; k++) {
            acc[4*k+0] += w0 * ev0[k].x; acc[4*k+0] += w1 * ev1[k].x;
            acc[4*k+1] += w0 * ev0[k].y; acc[4*k+1] += w1 * ev1[k].y;
            acc[4*k+2] += w0 * ev0[k].z; acc[4*k+2] += w1 * ev1[k].z;
            acc[4*k+3] += w0 * ev0[k].w; acc[4*k+3] += w1 * ev1[k].w;
        }
    }

    // ---- block combine ----
    if (lane == 0) sm_s[warp] = s;
#pragma unroll
    for (int k = 0; k < 8; k++)
        sm_acc[warp * 256 + k * 32 + lane] =
            make_float4(acc[4*k+0], acc[4*k+1], acc[4*k+2], acc[4*k+3]);
    __syncthreads();

    float4 rsum = make_float4(0.f, 0.f, 0.f, 0.f);
#pragma unroll
    for (int w = 0; w < WARPS; w++) {
        const float4 a = sm_acc[w * 256 + tid];
        rsum.x += a.x; rsum.y += a.y; rsum.z += a.z; rsum.w += a.w;
    }
    ((float4*)g_blk_acc)[bid * 256 + tid] = rsum;

    if (tid == 0) {
        float S = 0.0f;
#pragma unroll
        for (int w = 0; w < WARPS; w++) S += sm_s[w];
        g_blk_s[bid] = S;
    }

    // ---- grid-wide sync (monotonic ticket; all 256 blocks co-resident) ----
    __threadfence();
    __syncthreads();
    if (tid == 0) {
        const unsigned int ticket = atomicAdd(&g_done, 1u);
        const unsigned int target = (ticket / (unsigned)NBLK) * (unsigned)NBLK
                                    + (unsigned)NBLK;
        unsigned int v;
        do {
            asm volatile("ld.global.acquire.gpu.u32 %0, [%1];"
                         : "=r"(v) : "l"(&g_done));
        } while (v < target);
    }
    __syncthreads();
    __threadfence();

    // ---- phase 2: finalize ----
    {
        float v = g_blk_s[tid];                       // 256 values, L2-hot
#pragma unroll
        for (int o = 16; o > 0; o >>= 1)
            v += __shfl_xor_sync(0xffffffffu, v, o);
        if (lane == 0) sm_s[warp] = v;
        __syncthreads();
        if (tid == 0) {
            float S = 0.0f;
#pragma unroll
            for (int j = 0; j < 8; j++) S += sm_s[j];
            sInv = 1.0f / S;
        }
        __syncthreads();
    }
    const float invS = sInv;

    // weights: this block's 128 rows (escore chunk L2-hot)
    if (tid < ROWS_PB)
        out[1024 + bid * ROWS_PB + tid] = g_escore[bid * ROWS_PB + tid] * invS;

    // output: blocks 0..127 reduce 8 dims each over 256 partials
    if (bid < 128) {
        const int dl = tid & 7;
        const int ch = tid >> 3;              // 0..31
        float r = 0.0f;
#pragma unroll
        for (int j = 0; j < 8; j++) {
            const int idx = ch + 32 * j;      // 0..255
            r += g_blk_acc[idx * HDIM + bid * 8 + dl];
        }
        sm_red[ch * 8 + dl] = r;
        __syncthreads();
        if (tid < 8) {
            float t2 = 0.0f;
#pragma unroll
            for (int j = 0; j < 32; j++) t2 += sm_red[j * 8 + tid];
            out[bid * 8 + tid] = t2 * invS;
        }
    }
}

extern "C" void kernel_launch(void* const* d_in, const int* in_sizes, int n_in,
                              void* d_out, int out_size)
{
    // inputs: [0]=dec_h (unused), [1]=enc, [2]=attn_w, [3]=attn_b (unused)
    const float* enc    = (const float*)d_in[1];
    const float* attn_w = (const float*)d_in[2];
    float* out = (float*)d_out;

    fused_kernel<<<NBLK, 256>>>(enc, attn_w, out);
}

// round 10
// speedup vs baseline: 1.0061x; 1.0061x over previous
#include <cuda_runtime.h>
#include <cstdint>

// T=32768, H=1024, O=1024
//   scores[t] = enc[t,:] . w_enc  (softmax-invariant decoder term dropped)
//   weights   = softmax(scores)            -> d_out[1024 .. 1024+32768)
//   output[h] = sum_t weights[t]*enc[t,h]  -> d_out[0 .. 1024)
//
// pass1: pure-LDG streaming, REGISTER DOUBLE-BUFFERED: while row r is in the
//   dot->shuffle->exp->accumulate chain, row r+1's 8 LDG.128 are in flight.
//   Loads outstanding ~100% of the time (was ~60% -> DRAM% pinned at ~65).
//   + prefetch.global.L2 6 rows ahead covers DRAM->L2.
// finalize: proven R4 split kernel (L2-hot ~2.5us in the timed graph).

#define T_ROWS   32768
#define HDIM     1024
#define NBLK     256
#define WARPS    8
#define ROWS_PW  16     // rows per warp: 256*8*16 = 32768
#define ROWS_PB  128

__device__ float g_escore[T_ROWS];
__device__ float g_blk_s[NBLK];
__device__ float g_blk_acc[NBLK * HDIM];

#define LOAD_ROW(dst, rowp)                                   \
    _Pragma("unroll")                                         \
    for (int j = 0; j < 8; j++) dst[j] = (rowp)[j * 32 + lane];

#define PROCESS_ROW(ev, grow)                                 \
    do {                                                      \
        float da = 0.f, db = 0.f, dc = 0.f, dd = 0.f;         \
        _Pragma("unroll")                                     \
        for (int j = 0; j < 8; j++) {                         \
            const float4 w = s_w[j * 32 + lane];              \
            da += ev[j].x * w.x;  db += ev[j].y * w.y;        \
            dc += ev[j].z * w.z;  dd += ev[j].w * w.w;        \
        }                                                     \
        float d = (da + db) + (dc + dd);                      \
        _Pragma("unroll")                                     \
        for (int o = 16; o > 0; o >>= 1)                      \
            d += __shfl_xor_sync(0xffffffffu, d, o);          \
        const float we = __expf(d);                           \
        if (lane == 0) g_escore[grow] = we;                   \
        s += we;                                              \
        _Pragma("unroll")                                     \
        for (int j = 0; j < 8; j++) {                         \
            acc[4*j+0] += we * ev[j].x;                       \
            acc[4*j+1] += we * ev[j].y;                       \
            acc[4*j+2] += we * ev[j].z;                       \
            acc[4*j+3] += we * ev[j].w;                       \
        }                                                     \
    } while (0)

#define PREFETCH_ROW(ridx)                                    \
    do {                                                      \
        const int pf = min((ridx), T_ROWS - 1);               \
        const char* p = (const char*)(enc4 + (size_t)pf * 256) + lane * 128; \
        asm volatile("prefetch.global.L2 [%0];" :: "l"(p));   \
    } while (0)

__global__ __launch_bounds__(256, 2)
void pass1_kernel(const float* __restrict__ enc, const float* __restrict__ attn_w)
{
    __shared__ float4 s_w[256];              // w_enc, 4KB
    __shared__ float4 sm_acc[WARPS * 256];   // 32KB combine scratch
    __shared__ float  sm_s[WARPS];

    const int tid  = threadIdx.x;
    const int lane = tid & 31;
    const int warp = tid >> 5;
    const int bid  = blockIdx.x;

    // w_enc = attn_w[:, O:], O = 1024
    s_w[tid] = ((const float4*)(attn_w + 1024))[tid];
    __syncthreads();

    const float4* __restrict__ enc4 = (const float4*)enc;

    float acc[32];
#pragma unroll
    for (int i = 0; i < 32; i++) acc[i] = 0.0f;
    float s = 0.0f;

    const int row0 = bid * ROWS_PB + warp * ROWS_PW;
    const float4* __restrict__ rp = enc4 + (size_t)row0 * 256;

    float4 evA[8], evB[8];

    // software pipeline: evA <- row 0; prefetch the first window
    LOAD_ROW(evA, rp);
    PREFETCH_ROW(row0 + 4);
    PREFETCH_ROW(row0 + 5);

#pragma unroll
    for (int r = 0; r < ROWS_PW; r += 2) {
        // loads for row r+1 go in flight before row r's compute chain
        if (r + 1 < ROWS_PW) LOAD_ROW(evB, rp + (r + 1) * 256);
        PREFETCH_ROW(row0 + r + 6);
        PROCESS_ROW(evA, row0 + r);

        if (r + 2 < ROWS_PW) LOAD_ROW(evA, rp + (r + 2) * 256);
        PREFETCH_ROW(row0 + r + 7);
        if (r + 1 < ROWS_PW) PROCESS_ROW(evB, row0 + r + 1);
    }

    // ---- block combine ----
    if (lane == 0) sm_s[warp] = s;
#pragma unroll
    for (int k = 0; k < 8; k++)
        sm_acc[warp * 256 + k * 32 + lane] =
            make_float4(acc[4*k+0], acc[4*k+1], acc[4*k+2], acc[4*k+3]);
    __syncthreads();

    float4 rsum = make_float4(0.f, 0.f, 0.f, 0.f);
#pragma unroll
    for (int w = 0; w < WARPS; w++) {
        const float4 a = sm_acc[w * 256 + tid];
        rsum.x += a.x; rsum.y += a.y; rsum.z += a.z; rsum.w += a.w;
    }
    ((float4*)g_blk_acc)[bid * 256 + tid] = rsum;

    if (tid == 0) {
        float S = 0.0f;
#pragma unroll
        for (int w = 0; w < WARPS; w++) S += sm_s[w];
        g_blk_s[bid] = S;
    }
}

// grid = 160 blocks x 256 threads (proven R4 finalize).
//   blocks [0,128): weights  out[1024+t] = escore[t]*invS
//   blocks [128,160): output reduction over 256 partials, loads issued
//   before the invS chain so DRAM/L2 latency overlaps it.
__global__ __launch_bounds__(256)
void finalize_kernel(float* __restrict__ out)
{
    __shared__ float sws[8];
    __shared__ float sInv;
    __shared__ float sm2[8][32];

    const int tid  = threadIdx.x;
    const int lane = tid & 31;
    const int warp = tid >> 5;
    const int b    = blockIdx.x;

    // --- issue data loads first (independent of invS) ---
    float e = 0.0f, r = 0.0f;
    if (b < 128) {
        e = g_escore[b * 256 + tid];
    } else {
        const int d0 = (b - 128) * 32;
        const int dl = tid & 31;
        const int ch = tid >> 5;
#pragma unroll
        for (int w = 0; w < 32; w++) {           // ch + 8*w over 256 partials
            const int idx = ch + 8 * w;
            r += g_blk_acc[idx * HDIM + d0 + dl];
        }
    }

    // --- invS reduction (warp shuffle + 1 barrier round) ---
    float v = g_blk_s[tid];
#pragma unroll
    for (int o = 16; o > 0; o >>= 1)
        v += __shfl_xor_sync(0xffffffffu, v, o);
    if (lane == 0) sws[warp] = v;
    __syncthreads();
    if (tid == 0) {
        float S = 0.0f;
#pragma unroll
        for (int j = 0; j < 8; j++) S += sws[j];
        sInv = 1.0f / S;
    }
    __syncthreads();
    const float invS = sInv;

    if (b < 128) {
        out[1024 + b * 256 + tid] = e * invS;
    } else {
        const int d0 = (b - 128) * 32;
        const int dl = tid & 31;
        const int ch = tid >> 5;
        sm2[ch][dl] = r;
        __syncthreads();
        if (ch == 0) {
            float t2 = 0.0f;
#pragma unroll
            for (int j = 0; j < 8; j++) t2 += sm2[j][dl];
            out[d0 + dl] = t2 * invS;
        }
    }
}

extern "C" void kernel_launch(void* const* d_in, const int* in_sizes, int n_in,
                              void* d_out, int out_size)
{
    // inputs: [0]=dec_h (unused), [1]=enc, [2]=attn_w, [3]=attn_b (unused)
    const float* enc    = (const float*)d_in[1];
    const float* attn_w = (const float*)d_in[2];
    float* out = (float*)d_out;

    pass1_kernel<<<NBLK, 256>>>(enc, attn_w);
    finalize_kernel<<<160, 256>>>(out);
}